// round 16
// baseline (speedup 1.0000x reference)
#include <cuda_runtime.h>
#include <string.h>
#include <stdint.h>

#define EPS 1e-5f

// ---------------- folded-weight scratch (device globals: allowed) ----------
__device__ __align__(16) float g_W1t[512 * 192];     // [c][j], BN1 scale folded
__device__ __align__(16) float g_b1f[192];           // BN1 folded bias
__device__ __align__(16) float g_W4c[4 * 64 * 128];  // [chunk][d][cl], BN2 folded
__device__ __align__(16) float g_c4f[512];           // BN2 folded bias

// ---------------- prep: fold BN into weights (tiled transposes) ------------
__global__ void prep_kernel(const float* __restrict__ W123, const float* __restrict__ b123,
                            const float* __restrict__ g123, const float* __restrict__ be123,
                            const float* __restrict__ m123, const float* __restrict__ v123,
                            const float* __restrict__ W4,   const float* __restrict__ b4,
                            const float* __restrict__ g4,   const float* __restrict__ be4,
                            const float* __restrict__ m4,   const float* __restrict__ v4)
{
    __shared__ float tile[32][33];
    const int b  = blockIdx.x;
    const int tx = threadIdx.x & 31;
    const int ty = threadIdx.x >> 5;

    if (b < 96) {
        const int jt = b / 16, ct = b % 16;
        #pragma unroll
        for (int k = 0; k < 4; k++) {
            int jy = ty + k * 8;
            int j  = jt * 32 + jy, c = ct * 32 + tx;
            float s = g123[j] * rsqrtf(v123[j] + EPS);
            tile[jy][tx] = W123[j * 512 + c] * s;
        }
        __syncthreads();
        #pragma unroll
        for (int k = 0; k < 4; k++) {
            int cy = ty + k * 8;
            int c  = ct * 32 + cy, j = jt * 32 + tx;
            g_W1t[c * 192 + j] = tile[tx][cy];
        }
    } else if (b < 128) {
        const int bb = b - 96;
        const int dt = bb / 16, ct = bb % 16;
        #pragma unroll
        for (int k = 0; k < 4; k++) {
            int cy = ty + k * 8;
            int c  = ct * 32 + cy, d = dt * 32 + tx;
            float s = g4[c] * rsqrtf(v4[c] + EPS);
            tile[cy][tx] = W4[c * 64 + d] * s;
        }
        __syncthreads();
        #pragma unroll
        for (int k = 0; k < 4; k++) {
            int dy = ty + k * 8;
            int d  = dt * 32 + dy, c = ct * 32 + tx;
            g_W4c[(c >> 7) * 8192 + d * 128 + (c & 127)] = tile[tx][dy];
        }
    } else {
        int i = threadIdx.x;
        if (i < 192) {
            float s = g123[i] * rsqrtf(v123[i] + EPS);
            g_b1f[i] = (b123[i] - m123[i]) * s + be123[i];
        }
        for (int c = i; c < 512; c += 256) {
            float s = g4[c] * rsqrtf(v4[c] + EPS);
            g_c4f[c] = (b4[c] - m4[c]) * s + be4[c];
        }
    }
}

// ---------------- helpers ---------------------------------------------------
__device__ __forceinline__ float2 ffma2(float2 a, float2 b, float2 c) {
    unsigned long long au, bu, cu, du;
    memcpy(&au, &a, 8); memcpy(&bu, &b, 8); memcpy(&cu, &c, 8);
    asm("fma.rn.f32x2 %0, %1, %2, %3;" : "=l"(du) : "l"(au), "l"(bu), "l"(cu));
    float2 d; memcpy(&d, &du, 8); return d;
}
__device__ __forceinline__ uint32_t smem_u32(const void* p) {
    uint32_t a;
    asm("{ .reg .u64 t; cvta.to.shared.u64 t, %1; cvt.u32.u64 %0, t; }" : "=r"(a) : "l"(p));
    return a;
}
__device__ __forceinline__ void mbar_init(uint32_t a, uint32_t cnt) {
    asm volatile("mbarrier.init.shared.b64 [%0], %1;" :: "r"(a), "r"(cnt) : "memory");
}
__device__ __forceinline__ void mbar_expect_tx(uint32_t a, uint32_t bytes) {
    asm volatile("mbarrier.arrive.expect_tx.shared.b64 _, [%0], %1;" :: "r"(a), "r"(bytes) : "memory");
}
__device__ __forceinline__ void mbar_wait(uint32_t a, uint32_t parity) {
    asm volatile(
        "{\n\t.reg .pred P;\n\t"
        "WL%=:\n\t"
        "mbarrier.try_wait.parity.acquire.cta.shared::cta.b64 P, [%0], %1, 0x989680;\n\t"
        "@P bra WD%=;\n\t"
        "bra.uni WL%=;\n\t"
        "WD%=:\n\t}"
        :: "r"(a), "r"(parity) : "memory");
}
__device__ __forceinline__ void bulk_g2s(uint32_t dst_smem, const float* gsrc,
                                         uint32_t bytes, uint32_t mbar) {
    asm volatile(
        "cp.async.bulk.shared::cluster.global.mbarrier::complete_tx::bytes [%0], [%1], %2, [%3];"
        :: "r"(dst_smem), "l"(gsrc), "r"(bytes), "r"(mbar) : "memory");
}
#define NAMED_BAR(id) asm volatile("bar.sync %0, 192;" :: "r"(id) : "memory")
#define FENCE_ASYNC() asm volatile("fence.proxy.async.shared::cta;" ::: "memory")

// SMEM (floats), per 384-thread CTA (2 CTAs/SM):
//   [0, 18432)       A_T[512][36]
//                    post-GEMM1: partials [0,6144), then W4 chunks 2x8192 [0,16384)
//   [16384, 22528)   act[32][192] (alive only reduction->attention; disjoint in
//                    time from W4 chunk 1 tail? NO — W4 buf1 is [8192,16384),
//                    act starts at 16384: no overlap. ok)
//   [18432, 24576)   4 x 1536 GEMM1 weight stages (dead after GEMM1)
//   [18432, 26688)   yS 2 x 4128 (phase 3 only; act dead by then)
//   [26688, 28768)   sATT 8 x 260
//   [28768, 28780)   6 mbarriers
#define SMF 28784

__global__ void __launch_bounds__(384, 2)
fused_kernel(const float* __restrict__ x, float* __restrict__ out)
{
    extern __shared__ float sm[];
    float* sAT  = sm;
    float* act  = sm + 16384;
    float* sATT = sm + 26688;
    const uint32_t smb  = smem_u32(sm);
    const uint32_t smbW = smb + 18432u * 4u;
    const uint32_t MBAR = smb + 28768u * 4u;   // +8*i: i=0..3 W1 stages, 4..5 W4

    const int t    = threadIdx.x;
    const int warp = t >> 5;               // 12 warps
    const int lane = t & 31;
    const int kh   = (warp >= 6);          // K-half group
    const int wg   = kh ? warp - 6 : warp; // col tile 0..5 within group
    const int n0   = blockIdx.x * 8;

    const int r0 = (lane >> 3) * 8;        // 8 consecutive rows (of 32)
    const int j0 = wg * 32 + (lane & 7) * 4;   // 4 consecutive cols

    if (t == 0) {
        #pragma unroll
        for (int i = 0; i < 6; i++) mbar_init(MBAR + 8u * i, 1);
    }
    __syncthreads();
    if (t == 0) {
        #pragma unroll
        for (int bi = 0; bi < 4; bi++) {
            int kk2 = bi >> 1, st = bi & 1;
            mbar_expect_tx(MBAR + 8u * bi, 6144);
            bulk_g2s(smbW + 6144u * bi, g_W1t + kk2 * 49152 + st * 1536,
                     6144, MBAR + 8u * bi);
        }
    }

    const float4* xb = (const float4*)x;

    // ---- Phase 0: gather xs into A_T[c][row], row = 4*i + l
    {
        const int cl = lane >> 1;
        const int hs = lane & 1;
        for (int u = warp; u < 256; u += 12) {
            int i  = u >> 5, cb = u & 31;
            int c  = cb * 16 + cl;
            long f4 = ((long)(n0 + i) * 512 + c) * 4 + hs * 2;
            float4 v = __ldg(&xb[f4]);
            *(float2*)&sAT[c * 36 + 4 * i + 2 * hs] = make_float2(v.x, v.z);
        }
    }
    __syncthreads();

    // ---- Phase 1: GEMM1 [32r][192c]; 6 warps x (32r x 32c) per kh group;
    //      thread tile 8r x 4c row-pair packed; 32 stages of 8 k-rows.
    float2 acc[4][4];
    #pragma unroll
    for (int rp = 0; rp < 4; rp++)
        #pragma unroll
        for (int c = 0; c < 4; c++) acc[rp][c] = make_float2(0.f, 0.f);

    #define FMA16(A0, A1, B)                                                    \
        do {                                                                    \
            float2 bd0 = make_float2((B).x, (B).x);                             \
            float2 bd1 = make_float2((B).y, (B).y);                             \
            float2 bd2 = make_float2((B).z, (B).z);                             \
            float2 bd3 = make_float2((B).w, (B).w);                             \
            float2 p0 = make_float2((A0).x, (A0).y);                            \
            float2 p1 = make_float2((A0).z, (A0).w);                            \
            float2 p2 = make_float2((A1).x, (A1).y);                            \
            float2 p3 = make_float2((A1).z, (A1).w);                            \
            acc[0][0] = ffma2(p0, bd0, acc[0][0]);                              \
            acc[0][1] = ffma2(p0, bd1, acc[0][1]);                              \
            acc[0][2] = ffma2(p0, bd2, acc[0][2]);                              \
            acc[0][3] = ffma2(p0, bd3, acc[0][3]);                              \
            acc[1][0] = ffma2(p1, bd0, acc[1][0]);                              \
            acc[1][1] = ffma2(p1, bd1, acc[1][1]);                              \
            acc[1][2] = ffma2(p1, bd2, acc[1][2]);                              \
            acc[1][3] = ffma2(p1, bd3, acc[1][3]);                              \
            acc[2][0] = ffma2(p2, bd0, acc[2][0]);                              \
            acc[2][1] = ffma2(p2, bd1, acc[2][1]);                              \
            acc[2][2] = ffma2(p2, bd2, acc[2][2]);                              \
            acc[2][3] = ffma2(p2, bd3, acc[2][3]);                              \
            acc[3][0] = ffma2(p3, bd0, acc[3][0]);                              \
            acc[3][1] = ffma2(p3, bd1, acc[3][1]);                              \
            acc[3][2] = ffma2(p3, bd2, acc[3][2]);                              \
            acc[3][3] = ffma2(p3, bd3, acc[3][3]);                              \
        } while (0)

    for (int st = 0; st < 32; st++) {
        const int bi = kh * 2 + (st & 1);
        mbar_wait(MBAR + 8u * bi, (st >> 1) & 1);

        const float* wbuf  = sm + 18432 + bi * 1536 + j0;
        const float* abase = sAT + (kh * 256 + st * 8) * 36 + r0;

        float4 a0 = *(const float4*)&abase[0];
        float4 a1 = *(const float4*)&abase[4];
        float4 b  = *(const float4*)&wbuf[0];
        #pragma unroll 7
        for (int kk = 0; kk < 7; kk++) {
            float4 a0n = *(const float4*)&abase[(kk + 1) * 36];
            float4 a1n = *(const float4*)&abase[(kk + 1) * 36 + 4];
            float4 bn  = *(const float4*)&wbuf[(kk + 1) * 192];
            FMA16(a0, a1, b);
            a0 = a0n; a1 = a1n; b = bn;
        }
        FMA16(a0, a1, b);

        NAMED_BAR(1 + kh);                  // group consumed this buffer

        if (st + 2 < 32 && t == (kh ? 192 : 0)) {
            mbar_expect_tx(MBAR + 8u * bi, 6144);
            bulk_g2s(smbW + 6144u * bi, g_W1t + kh * 49152 + (st + 2) * 1536,
                     6144, MBAR + 8u * bi);
        }
    }
    __syncthreads();   // both groups done; A_T & weight stages dead

    // ---- K-split reduction: kh1 dumps partials [0,6144); kh0 adds+bias+relu
    if (kh == 1) {
        float* rb = sm + wg * 1024 + lane * 4;
        #pragma unroll
        for (int q = 0; q < 8; q++) {
            int rp = q >> 1, c0 = (q & 1) * 2;
            *(float4*)&rb[q * 128] = make_float4(acc[rp][c0].x, acc[rp][c0].y,
                                                 acc[rp][c0 + 1].x, acc[rp][c0 + 1].y);
        }
    }
    __syncthreads();
    if (kh == 0) {
        const float* rb = sm + wg * 1024 + lane * 4;
        #pragma unroll
        for (int q = 0; q < 8; q++) {
            int rp = q >> 1, c0 = (q & 1) * 2;
            float4 p = *(const float4*)&rb[q * 128];
            acc[rp][c0].x     += p.x;  acc[rp][c0].y     += p.y;
            acc[rp][c0 + 1].x += p.z;  acc[rp][c0 + 1].y += p.w;
        }
        float4 bias = __ldg((const float4*)&g_b1f[j0]);
        #pragma unroll
        for (int rp = 0; rp < 4; rp++) {
            float4 ev, od;
            ev.x = fmaxf(acc[rp][0].x + bias.x, 0.f);
            ev.y = fmaxf(acc[rp][1].x + bias.y, 0.f);
            ev.z = fmaxf(acc[rp][2].x + bias.z, 0.f);
            ev.w = fmaxf(acc[rp][3].x + bias.w, 0.f);
            od.x = fmaxf(acc[rp][0].y + bias.x, 0.f);
            od.y = fmaxf(acc[rp][1].y + bias.y, 0.f);
            od.z = fmaxf(acc[rp][2].y + bias.z, 0.f);
            od.w = fmaxf(acc[rp][3].y + bias.w, 0.f);
            *(float4*)&act[(r0 + rp * 2 + 0) * 192 + j0] = ev;
            *(float4*)&act[(r0 + rp * 2 + 1) * 192 + j0] = od;
        }
    }
    __syncthreads();   // act complete; partials dead

    // ---- W4 chunks 0,1 into [0,16384)
    if (t == 0) {
        FENCE_ASYNC();
        mbar_expect_tx(MBAR + 32, 32768);
        bulk_g2s(smb,          g_W4c,        32768, MBAR + 32);
        mbar_expect_tx(MBAR + 40, 32768);
        bulk_g2s(smb + 32768u, g_W4c + 8192, 32768, MBAR + 40);
    }

    // ---- Phase 2: warp-local 4x4 attention (warps 0..7, warp = sample)
    if (warp < 8) {
        const int s = warp, g = lane;
        float2 q2[4], k2[4], v2[4];
        #pragma unroll
        for (int l = 0; l < 4; l++) {
            const float* ar = act + (4 * s + l) * 192;
            q2[l] = *(const float2*)&ar[2 * g];
            k2[l] = *(const float2*)&ar[2 * g + 64];
            v2[l] = *(const float2*)&ar[2 * g + 128];
        }
        float sc[16];
        #pragma unroll
        for (int l = 0; l < 4; l++)
            #pragma unroll
            for (int m = 0; m < 4; m++)
                sc[l * 4 + m] = q2[l].x * k2[m].x + q2[l].y * k2[m].y;
        #pragma unroll
        for (int off = 16; off > 0; off >>= 1)
            #pragma unroll
            for (int i = 0; i < 16; i++)
                sc[i] += __shfl_xor_sync(0xffffffffu, sc[i], off);

        #pragma unroll
        for (int l = 0; l < 4; l++) {
            float s0 = sc[l*4+0], s1 = sc[l*4+1], s2 = sc[l*4+2], s3 = sc[l*4+3];
            float mx = fmaxf(fmaxf(s0, s1), fmaxf(s2, s3));
            float e0 = __expf(s0 - mx), e1 = __expf(s1 - mx);
            float e2 = __expf(s2 - mx), e3 = __expf(s3 - mx);
            float inv = 1.f / (e0 + e1 + e2 + e3);
            float ax = (e0*v2[0].x + e1*v2[1].x + e2*v2[2].x + e3*v2[3].x) * inv;
            float ay = (e0*v2[0].y + e1*v2[1].y + e2*v2[2].y + e3*v2[3].y) * inv;
            sATT[s * 260 + (2*g)   * 4 + l] = ax;
            sATT[s * 260 + (2*g+1) * 4 + l] = ay;
        }
    }
    __syncthreads();   // sATT complete; act dead

    // ---- Phase 3: GEMM2 (warps 0..7) + epilogue (warps 8..11) alternation
    const int sI  = lane & 7;
    const int cgr = lane >> 3;             // 0..3 -> 16 channels per warp

    auto ybuf = [&](int cc) -> float* { return sm + 18432 + (cc & 1) * 4128; };

    auto compute_y = [&](int cc) {
        float* yb = ybuf(cc);
        const int cb = cc * 128 + warp * 16 + cgr * 4;
        float2 y01[4], y23[4];
        #pragma unroll
        for (int cp = 0; cp < 4; cp++) {
            y01[cp] = make_float2(0.f, 0.f);
            y23[cp] = make_float2(0.f, 0.f);
        }
        const float* attn = sATT + sI * 260;
        const float* wp   = sm + (cc & 1) * 8192 + warp * 16 + cgr * 4;
        float4 av = *(const float4*)&attn[0];
        float4 wv = *(const float4*)&wp[0];
        #pragma unroll 7
        for (int d = 0; d < 63; d++) {
            float4 avn = *(const float4*)&attn[(d + 1) * 4];
            float4 wvn = *(const float4*)&wp[(d + 1) * 128];
            float2 a01 = make_float2(av.x, av.y), a23 = make_float2(av.z, av.w);
            const float* wvp = &wv.x;
            #pragma unroll
            for (int cp = 0; cp < 4; cp++) {
                float2 wb = make_float2(wvp[cp], wvp[cp]);
                y01[cp] = ffma2(a01, wb, y01[cp]);
                y23[cp] = ffma2(a23, wb, y23[cp]);
            }
            av = avn; wv = wvn;
        }
        {
            float2 a01 = make_float2(av.x, av.y), a23 = make_float2(av.z, av.w);
            const float* wvp = &wv.x;
            #pragma unroll
            for (int cp = 0; cp < 4; cp++) {
                float2 wb = make_float2(wvp[cp], wvp[cp]);
                y01[cp] = ffma2(a01, wb, y01[cp]);
                y23[cp] = ffma2(a23, wb, y23[cp]);
            }
        }
        float4 cf = __ldg((const float4*)&g_c4f[cb]);
        const float* cfp = &cf.x;
        const int fb = (warp * 16 + cgr * 4) * 4;
        #pragma unroll
        for (int cp = 0; cp < 4; cp++) {
            *(float4*)&yb[sI * 516 + fb + cp * 4] =
                make_float4(y01[cp].x + cfp[cp], y01[cp].y + cfp[cp],
                            y23[cp].x + cfp[cp], y23[cp].y + cfp[cp]);
        }
    };
    auto epilogue = [&](int cc, int wfirst, int wcount) {
        const float* ys = ybuf(cc);
        for (int u = warp - wfirst; u < 128; u += wcount) {
            const int s = u >> 4, i = u & 15;
            const int f = i * 32 + lane;
            float yv = ys[s * 516 + f];
            long b4i = ((long)(n0 + s) * 512 + cc * 128) * 4 + f;
            float4 v = __ldg(&xb[b4i]);
            v.x += yv; v.y += yv; v.z += yv; v.w += yv;
            ((float4*)out)[b4i] = v;
        }
    };

    mbar_wait(MBAR + 32, 0);               // chunk 0 resident
    if (warp < 8) compute_y(0);
    __syncthreads();
    if (t == 0) {
        mbar_expect_tx(MBAR + 32, 32768);
        bulk_g2s(smb, g_W4c + 2 * 8192, 32768, MBAR + 32);      // chunk 2 -> buf0
    }
    #pragma unroll
    for (int cc = 1; cc < 4; cc++) {
        mbar_wait(MBAR + 32u + 8u * (cc & 1), (cc >> 1) & 1);
        if (warp < 8) compute_y(cc);
        else          epilogue(cc - 1, 8, 4);
        __syncthreads();
        if (cc == 1 && t == 0) {
            mbar_expect_tx(MBAR + 40, 32768);
            bulk_g2s(smb + 32768u, g_W4c + 3 * 8192, 32768, MBAR + 40);   // chunk 3
        }
    }
    epilogue(3, 0, 12);
}

extern "C" void kernel_launch(void* const* d_in, const int* in_sizes, int n_in,
                              void* d_out, int out_size)
{
    const float* x    = (const float*)d_in[0];
    const float* W123 = (const float*)d_in[1];
    const float* b123 = (const float*)d_in[2];
    const float* g123 = (const float*)d_in[3];
    const float* be123= (const float*)d_in[4];
    const float* m123 = (const float*)d_in[5];
    const float* v123 = (const float*)d_in[6];
    const float* W4   = (const float*)d_in[7];
    const float* b4   = (const float*)d_in[8];
    const float* g4   = (const float*)d_in[9];
    const float* be4  = (const float*)d_in[10];
    const float* m4   = (const float*)d_in[11];
    const float* v4   = (const float*)d_in[12];

    int N = in_sizes[0] / (512 * 16);   // 2048

    prep_kernel<<<129, 256>>>(W123, b123, g123, be123, m123, v123,
                              W4, b4, g4, be4, m4, v4);

    cudaFuncSetAttribute(fused_kernel, cudaFuncAttributeMaxDynamicSharedMemorySize,
                         SMF * 4);
    fused_kernel<<<N / 8, 384, SMF * 4>>>(x, (float*)d_out);
}